// round 16
// baseline (speedup 1.0000x reference)
#include <cuda_runtime.h>
#include <cstdint>

#define FULL_MASK 0xffffffffu

// Problem constants: B=4, N=2048, DIM=1024, H=16, d=64
static constexpr int SEQ = 2048;
static constexpr int DIMC = 1024;

// Q/K/V head-split scratch [B,H,N,64] (tf32-rounded fp32; Q scaled by log2e/8).
__device__ float g_Q[4 * 2048 * 1024];
__device__ float g_K[4 * 2048 * 1024];
__device__ float g_V[4 * 2048 * 1024];

static __device__ __forceinline__ float to_tf32(float x) {
    uint32_t u;
    asm("cvt.rna.tf32.f32 %0, %1;" : "=r"(u) : "f"(x));
    return __uint_as_float(u);
}
static __device__ __forceinline__ uint32_t fbits(float x) { return __float_as_uint(x); }

static __device__ __forceinline__ void mma_tf32(float c[4], const uint32_t a[4],
                                                uint32_t b0, uint32_t b1) {
    asm("mma.sync.aligned.m16n8k8.row.col.f32.tf32.tf32.f32 "
        "{%0,%1,%2,%3},{%4,%5,%6,%7},{%8,%9},{%0,%1,%2,%3};"
        : "+f"(c[0]), "+f"(c[1]), "+f"(c[2]), "+f"(c[3])
        : "r"(a[0]), "r"(a[1]), "r"(a[2]), "r"(a[3]), "r"(b0), "r"(b1));
}

static __device__ __forceinline__ uint32_t smem_u32(const void* p) {
    return (uint32_t)__cvta_generic_to_shared(p);
}
static __device__ __forceinline__ void cp16(uint32_t dst, const void* src) {
    asm volatile("cp.async.cg.shared.global [%0], [%1], 16;" :: "r"(dst), "l"(src));
}
static __device__ __forceinline__ void cp_commit() {
    asm volatile("cp.async.commit_group;");
}
template <int N>
static __device__ __forceinline__ void cp_wait() {
    asm volatile("cp.async.wait_group %0;" :: "n"(N));
}

// C[m][n] = sum_k A[m][k] * W[n][k]; stores to_tf32(C * scale), head-split layout.
// Software-pipelined: next k-slab's LDGs issue before the MMA block.
__global__ void __launch_bounds__(256) proj_gemm(const float* __restrict__ A,
                                                 const float* __restrict__ W,
                                                 float* __restrict__ Out,
                                                 float scale) {
    __shared__ float As[128][36];
    __shared__ float Bs[128][36];
    const int tid = threadIdx.x;
    const int lane = tid & 31;
    const int warp = tid >> 5;
    const int wm = warp & 1;
    const int wn = warp >> 1;
    const int mBase = blockIdx.y * 128;
    const int nBase = blockIdx.x * 128;

    float c[4][4][4];
#pragma unroll
    for (int i = 0; i < 4; i++)
#pragma unroll
        for (int j = 0; j < 4; j++)
#pragma unroll
            for (int k = 0; k < 4; k++) c[i][j][k] = 0.f;

    const int ldRow = tid >> 3;
    const int ldCol = (tid & 7) << 2;

    float4 ra[4], rb[4];
#pragma unroll
    for (int p = 0; p < 4; p++) {
        ra[p] = *(const float4*)&A[(size_t)(mBase + ldRow + 32 * p) * DIMC + ldCol];
        rb[p] = *(const float4*)&W[(size_t)(nBase + ldRow + 32 * p) * DIMC + ldCol];
    }

    for (int k0 = 0; k0 < DIMC; k0 += 32) {
        __syncthreads();
#pragma unroll
        for (int p = 0; p < 4; p++) {
            float4 ta;
            ta.x = to_tf32(ra[p].x); ta.y = to_tf32(ra[p].y);
            ta.z = to_tf32(ra[p].z); ta.w = to_tf32(ra[p].w);
            *(float4*)&As[ldRow + 32 * p][ldCol] = ta;
            float4 tb;
            tb.x = to_tf32(rb[p].x); tb.y = to_tf32(rb[p].y);
            tb.z = to_tf32(rb[p].z); tb.w = to_tf32(rb[p].w);
            *(float4*)&Bs[ldRow + 32 * p][ldCol] = tb;
        }
        __syncthreads();

        if (k0 + 32 < DIMC) {
            const int kn = k0 + 32;
#pragma unroll
            for (int p = 0; p < 4; p++) {
                ra[p] = *(const float4*)&A[(size_t)(mBase + ldRow + 32 * p) * DIMC + kn + ldCol];
                rb[p] = *(const float4*)&W[(size_t)(nBase + ldRow + 32 * p) * DIMC + kn + ldCol];
            }
        }

#pragma unroll
        for (int kk = 0; kk < 32; kk += 8) {
            uint32_t a[4][4];
#pragma unroll
            for (int mi = 0; mi < 4; mi++) {
                const int r = wm * 64 + mi * 16 + (lane >> 2);
                const int col = kk + (lane & 3);
                a[mi][0] = fbits(As[r][col]);
                a[mi][1] = fbits(As[r + 8][col]);
                a[mi][2] = fbits(As[r][col + 4]);
                a[mi][3] = fbits(As[r + 8][col + 4]);
            }
#pragma unroll
            for (int nf = 0; nf < 4; nf++) {
                const int n = wn * 32 + nf * 8 + (lane >> 2);
                const int col = kk + (lane & 3);
                const uint32_t b0 = fbits(Bs[n][col]);
                const uint32_t b1 = fbits(Bs[n][col + 4]);
#pragma unroll
                for (int mi = 0; mi < 4; mi++) mma_tf32(c[mi][nf], a[mi], b0, b1);
            }
        }
    }

#pragma unroll
    for (int mi = 0; mi < 4; mi++) {
        const int gm = mBase + wm * 64 + mi * 16 + (lane >> 2);
        const int b = gm >> 11;
        const int n = gm & 2047;
#pragma unroll
        for (int nf = 0; nf < 4; nf++) {
            const int gn = nBase + wn * 32 + nf * 8 + ((lane & 3) << 1);
            const int h = gn >> 6;
            const int j = gn & 63;
            const size_t base = (((size_t)(b * 16 + h) * SEQ) + n) * 64 + j;
            *(float2*)&Out[base] =
                make_float2(to_tf32(c[mi][nf][0] * scale), to_tf32(c[mi][nf][1] * scale));
            *(float2*)&Out[base + 8 * 64] =
                make_float2(to_tf32(c[mi][nf][2] * scale), to_tf32(c[mi][nf][3] * scale));
        }
    }
}

// Fused K+V projection, 512 threads / 16 warps: warps 0-7 compute K, warps
// 8-15 compute V (each warp a 64x32 output tile). ONE shared A (kv) staging
// stream like the 256-thread version, but 64 accum regs/thread instead of 128
// -> ~120 regs -> 16 warps/SM (4/SMSP) instead of 8.
__global__ void __launch_bounds__(512, 1) proj_kv(const float* __restrict__ A,
                                                  const float* __restrict__ Wk,
                                                  const float* __restrict__ Wv,
                                                  float* __restrict__ OutK,
                                                  float* __restrict__ OutV) {
    // dynamic smem: As[128][36] @0, Bk[128][36] @4608, Bv[128][36] @9216 (floats)
    extern __shared__ float psm[];
    float (*As)[36] = (float (*)[36])psm;
    float (*Bk)[36] = (float (*)[36])(psm + 4608);
    float (*Bv)[36] = (float (*)[36])(psm + 9216);

    const int tid = threadIdx.x;
    const int lane = tid & 31;
    const int warp = tid >> 5;
    const int mat = warp >> 3;         // 0 = K, 1 = V
    const int w8 = warp & 7;
    const int wm = w8 & 1;             // 2 m-halves of 64
    const int wn = w8 >> 1;            // 4 n-quarters of 32
    const int mBase = blockIdx.y * 128;
    const int nBase = blockIdx.x * 128;

    float c[4][4][4];
#pragma unroll
    for (int i = 0; i < 4; i++)
#pragma unroll
        for (int j = 0; j < 4; j++)
#pragma unroll
            for (int k = 0; k < 4; k++) c[i][j][k] = 0.f;

    // Staging: 512 threads, each loads 8 floats (2 float4) of A, Bk, Bv per slab.
    const int ldRow = tid >> 2;            // 0..127
    const int ldCol = (tid & 3) << 3;      // 0, 8, 16, 24

    float4 ra[2], rbk[2], rbv[2];
#pragma unroll
    for (int p = 0; p < 2; p++) {
        const size_t rowA = (size_t)(mBase + ldRow) * DIMC + ldCol + 4 * p;
        const size_t rowB = (size_t)(nBase + ldRow) * DIMC + ldCol + 4 * p;
        ra[p]  = *(const float4*)&A[rowA];
        rbk[p] = *(const float4*)&Wk[rowB];
        rbv[p] = *(const float4*)&Wv[rowB];
    }

    for (int k0 = 0; k0 < DIMC; k0 += 32) {
        __syncthreads();
#pragma unroll
        for (int p = 0; p < 2; p++) {
            float4 t;
            t.x = to_tf32(ra[p].x); t.y = to_tf32(ra[p].y);
            t.z = to_tf32(ra[p].z); t.w = to_tf32(ra[p].w);
            *(float4*)&As[ldRow][ldCol + 4 * p] = t;
            t.x = to_tf32(rbk[p].x); t.y = to_tf32(rbk[p].y);
            t.z = to_tf32(rbk[p].z); t.w = to_tf32(rbk[p].w);
            *(float4*)&Bk[ldRow][ldCol + 4 * p] = t;
            t.x = to_tf32(rbv[p].x); t.y = to_tf32(rbv[p].y);
            t.z = to_tf32(rbv[p].z); t.w = to_tf32(rbv[p].w);
            *(float4*)&Bv[ldRow][ldCol + 4 * p] = t;
        }
        __syncthreads();

        if (k0 + 32 < DIMC) {
            const int kn = k0 + 32;
#pragma unroll
            for (int p = 0; p < 2; p++) {
                const size_t rowA = (size_t)(mBase + ldRow) * DIMC + kn + ldCol + 4 * p;
                const size_t rowB = (size_t)(nBase + ldRow) * DIMC + kn + ldCol + 4 * p;
                ra[p]  = *(const float4*)&A[rowA];
                rbk[p] = *(const float4*)&Wk[rowB];
                rbv[p] = *(const float4*)&Wv[rowB];
            }
        }

        const float(*Bs)[36] = mat ? Bv : Bk;
#pragma unroll
        for (int kk = 0; kk < 32; kk += 8) {
            uint32_t a[4][4];
#pragma unroll
            for (int mi = 0; mi < 4; mi++) {
                const int r = wm * 64 + mi * 16 + (lane >> 2);
                const int col = kk + (lane & 3);
                a[mi][0] = fbits(As[r][col]);
                a[mi][1] = fbits(As[r + 8][col]);
                a[mi][2] = fbits(As[r][col + 4]);
                a[mi][3] = fbits(As[r + 8][col + 4]);
            }
#pragma unroll
            for (int nf = 0; nf < 4; nf++) {
                const int n = wn * 32 + nf * 8 + (lane >> 2);
                const int col = kk + (lane & 3);
                const uint32_t b0 = fbits(Bs[n][col]);
                const uint32_t b1 = fbits(Bs[n][col + 4]);
#pragma unroll
                for (int mi = 0; mi < 4; mi++) mma_tf32(c[mi][nf], a[mi], b0, b1);
            }
        }
    }

    float* Out = mat ? OutV : OutK;
#pragma unroll
    for (int mi = 0; mi < 4; mi++) {
        const int gm = mBase + wm * 64 + mi * 16 + (lane >> 2);
        const int b = gm >> 11;
        const int n = gm & 2047;
#pragma unroll
        for (int nf = 0; nf < 4; nf++) {
            const int gn = nBase + wn * 32 + nf * 8 + ((lane & 3) << 1);
            const int h = gn >> 6;
            const int j = gn & 63;
            const size_t base = (((size_t)(b * 16 + h) * SEQ) + n) * 64 + j;
            *(float2*)&Out[base] =
                make_float2(to_tf32(c[mi][nf][0]), to_tf32(c[mi][nf][1]));
            *(float2*)&Out[base + 8 * 64] =
                make_float2(to_tf32(c[mi][nf][2]), to_tf32(c[mi][nf][3]));
        }
    }
}

// Flash attention, single-pass streaming softmax. Q lives in PERSISTENT smem
// so registers fit 3 CTAs/SM (12 warps). K/V double-buffered cp.async; V rows
// permuted even-first so the S C-fragment feeds PV as an A-fragment with no
// shuffles; row-sum l computed by the PV MMA via a ones-column in the V tile
// padding; P fed as raw fp32 (HW tf32 truncation, bias cancels in O/l).
// Smem floats: Qs[128][68] @0 (8704), K 2x[32][68] @8704, V 2x[32][72] @13056.
static constexpr int ATTN_SMEM_FLOATS = 128 * 68 + 2 * 32 * 68 + 2 * 32 * 72;  // 17664
__global__ void __launch_bounds__(128, 3) attn(const float* __restrict__ Q,
                                               const float* __restrict__ K,
                                               const float* __restrict__ V,
                                               float* __restrict__ Out) {
    extern __shared__ float sm[];
    float (*Qs)[68] = (float (*)[68])sm;

    const int tid = threadIdx.x;
    const int lane = tid & 31;
    const int warp = tid >> 5;
    const int bh = blockIdx.y;
    const int qBase = blockIdx.x * 128;
    const float* Qg = Q + (size_t)bh * SEQ * 64;
    const float* Kg = K + (size_t)bh * SEQ * 64;
    const float* Vg = V + (size_t)bh * SEQ * 64;

    // --- Prologue: stage 128 Q rows into persistent smem ---
    {
        const int r = tid >> 4;
        const int cc = (tid & 15) << 2;
#pragma unroll
        for (int p = 0; p < 16; p++)
            *(float4*)&Qs[r + 8 * p][cc] =
                *(const float4*)&Qg[(size_t)(qBase + r + 8 * p) * 64 + cc];
    }

    // Ones-column init: V tile cols 64..71 (never touched by cp.async).
    // col 64 = 1.0 (l accumulator column), 65..71 = 0. Both buffers.
    if (tid < 64) {
        const int buf = tid >> 5;
        const int row = tid & 31;
        float* p = &sm[13056 + buf * 2304 + row * 72 + 64];
        *(float4*)&p[0] = make_float4(1.f, 0.f, 0.f, 0.f);
        *(float4*)&p[4] = make_float4(0.f, 0.f, 0.f, 0.f);
    }

    const int chRow = tid >> 4;            // rows 0..7 (+8 per i)
    const int chCol = (tid & 15) << 2;     // float col 0..60
    const int vRow = (chRow >> 1) + ((chRow & 1) << 2);  // even-first permutation
    const uint32_t kDst0 = smem_u32(&sm[8704]) + (uint32_t)(chRow * 68 + chCol) * 4u;
    const uint32_t vDst0 = smem_u32(&sm[13056]) + (uint32_t)(vRow * 72 + chCol) * 4u;

    auto issue_tile = [&](int t) {
        const int buf = t & 1;
        const int kvBase = t * 32;
        const uint32_t kD = kDst0 + buf * (2176 * 4);
        const uint32_t vD = vDst0 + buf * (2304 * 4);
#pragma unroll
        for (int i = 0; i < 4; i++) {
            const int row = chRow + 8 * i;
            cp16(kD + i * (8 * 68 * 4), &Kg[(size_t)(kvBase + row) * 64 + chCol]);
            cp16(vD + i * (8 * 72 * 4), &Vg[(size_t)(kvBase + row) * 64 + chCol]);
        }
        cp_commit();
    };

    constexpr int T = SEQ / 32;
    issue_tile(0);
    issue_tile(1);
    __syncthreads();   // Q staging + ones-columns visible to all warps

    // Accumulators: nf 0..7 = O columns, nf 8 = {l, garbage} columns 64..71.
    float o[2][9][4];
#pragma unroll
    for (int mi = 0; mi < 2; mi++)
#pragma unroll
        for (int nf = 0; nf < 9; nf++)
#pragma unroll
            for (int k = 0; k < 4; k++) o[mi][nf][k] = 0.f;

    const int rq = warp * 32 + (lane >> 2);

    for (int t = 0; t < T; t++) {
        if (t < T - 1) cp_wait<1>(); else cp_wait<0>();
        __syncthreads();

        const int buf = t & 1;
        const float(*Ks)[68] = (const float(*)[68])&sm[8704 + buf * 2176];
        const float(*Vs)[72] = (const float(*)[72])&sm[13056 + buf * 2304];

        // S = Q K^T (log2-domain: Q pre-scaled by log2e/8).
        // Q fragments re-read from smem each kk; each K B-frag feeds 2 MMAs.
        float s[2][4][4];
#pragma unroll
        for (int mi = 0; mi < 2; mi++)
#pragma unroll
            for (int nf = 0; nf < 4; nf++)
#pragma unroll
                for (int k = 0; k < 4; k++) s[mi][nf][k] = 0.f;

#pragma unroll
        for (int kk = 0; kk < 8; kk++) {
            const int col = kk * 8 + (lane & 3);
            uint32_t a0[4], a1[4];
            a0[0] = fbits(Qs[rq][col]);
            a0[1] = fbits(Qs[rq + 8][col]);
            a0[2] = fbits(Qs[rq][col + 4]);
            a0[3] = fbits(Qs[rq + 8][col + 4]);
            a1[0] = fbits(Qs[rq + 16][col]);
            a1[1] = fbits(Qs[rq + 24][col]);
            a1[2] = fbits(Qs[rq + 16][col + 4]);
            a1[3] = fbits(Qs[rq + 24][col + 4]);
#pragma unroll
            for (int nf = 0; nf < 4; nf++) {
                const int n = nf * 8 + (lane >> 2);
                const uint32_t b0 = fbits(Ks[n][col]);
                const uint32_t b1 = fbits(Ks[n][col + 4]);
                mma_tf32(s[0][nf], a0, b0, b1);
                mma_tf32(s[1][nf], a1, b0, b1);
            }
        }

        // p = exp2(s); no scalar l accumulation (handled by the ones-column MMA)
#pragma unroll
        for (int mi = 0; mi < 2; mi++)
#pragma unroll
            for (int nf = 0; nf < 4; nf++) {
                s[mi][nf][0] = exp2f(s[mi][nf][0]);
                s[mi][nf][1] = exp2f(s[mi][nf][1]);
                s[mi][nf][2] = exp2f(s[mi][nf][2]);
                s[mi][nf][3] = exp2f(s[mi][nf][3]);
            }

        // O += P V (and l += P·1 via nf=8), shuffle-free via the even-first V
        // row permutation; P fed as raw fp32 (HW tf32 truncation).
#pragma unroll
        for (int kt = 0; kt < 4; kt++) {
            uint32_t a0[4], a1[4];
            a0[0] = fbits(s[0][kt][0]);
            a0[1] = fbits(s[0][kt][2]);
            a0[2] = fbits(s[0][kt][1]);
            a0[3] = fbits(s[0][kt][3]);
            a1[0] = fbits(s[1][kt][0]);
            a1[1] = fbits(s[1][kt][2]);
            a1[2] = fbits(s[1][kt][1]);
            a1[3] = fbits(s[1][kt][3]);
#pragma unroll
            for (int nf = 0; nf < 9; nf++) {
                const int n = nf * 8 + (lane >> 2);
                const uint32_t b0 = fbits(Vs[kt * 8 + (lane & 3)][n]);
                const uint32_t b1 = fbits(Vs[kt * 8 + (lane & 3) + 4][n]);
                mma_tf32(o[0][nf], a0, b0, b1);
                mma_tf32(o[1][nf], a1, b0, b1);
            }
        }

        __syncthreads();   // all warps done with buf before it is refilled
        if (t + 2 < T) issue_tile(t + 2);
    }

    // l lives in column 64 = C-frag regs {0,2} of lanes with (lane&3)==0.
    // Broadcast from the quad leader to all 4 lanes.
    const int qlead = lane & ~3;
    float ls[2][2];
#pragma unroll
    for (int mi = 0; mi < 2; mi++) {
        ls[mi][0] = __shfl_sync(FULL_MASK, o[mi][8][0], qlead);
        ls[mi][1] = __shfl_sync(FULL_MASK, o[mi][8][2], qlead);
    }

    // epilogue: Out[b, q, h*64 + j] = O / l
    const int b = bh >> 4;
    const int h = bh & 15;
#pragma unroll
    for (int mi = 0; mi < 2; mi++) {
        const float inv0 = 1.f / ls[mi][0];
        const float inv1 = 1.f / ls[mi][1];
        const int r0 = qBase + warp * 32 + mi * 16 + (lane >> 2);
#pragma unroll
        for (int nf = 0; nf < 8; nf++) {
            const int col = h * 64 + nf * 8 + ((lane & 3) << 1);
            const size_t i0 = ((size_t)b * SEQ + r0) * DIMC + col;
            *(float2*)&Out[i0] =
                make_float2(o[mi][nf][0] * inv0, o[mi][nf][1] * inv0);
            *(float2*)&Out[i0 + (size_t)8 * DIMC] =
                make_float2(o[mi][nf][2] * inv1, o[mi][nf][3] * inv1);
        }
    }
}

extern "C" void kernel_launch(void* const* d_in, const int* in_sizes, int n_in,
                              void* d_out, int out_size) {
    const float* x  = (const float*)d_in[0];
    const float* kv = (const float*)d_in[1];
    const float* Wq = (const float*)d_in[2];
    const float* Wk = (const float*)d_in[3];
    const float* Wv = (const float*)d_in[4];
    float* out = (float*)d_out;

    float *Qg, *Kg, *Vg;
    cudaGetSymbolAddress((void**)&Qg, g_Q);
    cudaGetSymbolAddress((void**)&Kg, g_K);
    cudaGetSymbolAddress((void**)&Vg, g_V);

    // One-time host-object setup (no device memory: streams/events/attrs only).
    static cudaStream_t s2 = nullptr;
    static cudaEvent_t eFork = nullptr, eJoin = nullptr;
    if (s2 == nullptr) {
        cudaStreamCreateWithFlags(&s2, cudaStreamNonBlocking);
        cudaEventCreateWithFlags(&eFork, cudaEventDisableTiming);
        cudaEventCreateWithFlags(&eJoin, cudaEventDisableTiming);
        cudaFuncSetAttribute(proj_kv, cudaFuncAttributeMaxDynamicSharedMemorySize,
                             3 * 128 * 36 * 4);   // 55296 bytes
        cudaFuncSetAttribute(attn, cudaFuncAttributeMaxDynamicSharedMemorySize,
                             ATTN_SMEM_FLOATS * 4);   // 70656 bytes
    }

    // Fold (1/sqrt(64)) * log2(e) into the Q projection so the attention
    // softmax uses bare exp2.
    const float qscale = 0.125f * 1.44269504088896f;

    dim3 gg(DIMC / 128, (4 * SEQ) / 128);   // (8, 64)

    // Fork: Q projection on s2 concurrently with the fused K/V projection on
    // the main (captured) stream; join before attn.
    cudaEventRecord(eFork, 0);
    cudaStreamWaitEvent(s2, eFork, 0);
    proj_gemm<<<gg, 256, 0, s2>>>(x, Wq, Qg, qscale);
    proj_kv<<<gg, 512, 3 * 128 * 36 * 4>>>(kv, Wk, Wv, Kg, Vg);
    cudaEventRecord(eJoin, s2);
    cudaStreamWaitEvent(0, eJoin, 0);

    attn<<<dim3(SEQ / 128, 64), 128, ATTN_SMEM_FLOATS * 4>>>(Qg, Kg, Vg, out);
}

// round 17
// speedup vs baseline: 1.0376x; 1.0376x over previous
#include <cuda_runtime.h>
#include <cstdint>

#define FULL_MASK 0xffffffffu

// Problem constants: B=4, N=2048, DIM=1024, H=16, d=64
static constexpr int SEQ = 2048;
static constexpr int DIMC = 1024;

// Q/K/V head-split scratch [B,H,N,64] (tf32-rounded fp32; Q scaled by log2e/8).
__device__ float g_Q[4 * 2048 * 1024];
__device__ float g_K[4 * 2048 * 1024];
__device__ float g_V[4 * 2048 * 1024];

static __device__ __forceinline__ float to_tf32(float x) {
    uint32_t u;
    asm("cvt.rna.tf32.f32 %0, %1;" : "=r"(u) : "f"(x));
    return __uint_as_float(u);
}
static __device__ __forceinline__ uint32_t fbits(float x) { return __float_as_uint(x); }

static __device__ __forceinline__ void mma_tf32(float c[4], const uint32_t a[4],
                                                uint32_t b0, uint32_t b1) {
    asm("mma.sync.aligned.m16n8k8.row.col.f32.tf32.tf32.f32 "
        "{%0,%1,%2,%3},{%4,%5,%6,%7},{%8,%9},{%0,%1,%2,%3};"
        : "+f"(c[0]), "+f"(c[1]), "+f"(c[2]), "+f"(c[3])
        : "r"(a[0]), "r"(a[1]), "r"(a[2]), "r"(a[3]), "r"(b0), "r"(b1));
}

static __device__ __forceinline__ uint32_t smem_u32(const void* p) {
    return (uint32_t)__cvta_generic_to_shared(p);
}
static __device__ __forceinline__ void cp16(uint32_t dst, const void* src) {
    asm volatile("cp.async.cg.shared.global [%0], [%1], 16;" :: "r"(dst), "l"(src));
}
static __device__ __forceinline__ void cp_commit() {
    asm volatile("cp.async.commit_group;");
}
template <int N>
static __device__ __forceinline__ void cp_wait() {
    asm volatile("cp.async.wait_group %0;" :: "n"(N));
}

// C[m][n] = sum_k A[m][k] * W[n][k]; stores to_tf32(C * scale), head-split layout.
// Software-pipelined: next k-slab's LDGs issue before the MMA block.
__global__ void __launch_bounds__(256) proj_gemm(const float* __restrict__ A,
                                                 const float* __restrict__ W,
                                                 float* __restrict__ Out,
                                                 float scale) {
    __shared__ float As[128][36];
    __shared__ float Bs[128][36];
    const int tid = threadIdx.x;
    const int lane = tid & 31;
    const int warp = tid >> 5;
    const int wm = warp & 1;
    const int wn = warp >> 1;
    const int mBase = blockIdx.y * 128;
    const int nBase = blockIdx.x * 128;

    float c[4][4][4];
#pragma unroll
    for (int i = 0; i < 4; i++)
#pragma unroll
        for (int j = 0; j < 4; j++)
#pragma unroll
            for (int k = 0; k < 4; k++) c[i][j][k] = 0.f;

    const int ldRow = tid >> 3;
    const int ldCol = (tid & 7) << 2;

    float4 ra[4], rb[4];
#pragma unroll
    for (int p = 0; p < 4; p++) {
        ra[p] = *(const float4*)&A[(size_t)(mBase + ldRow + 32 * p) * DIMC + ldCol];
        rb[p] = *(const float4*)&W[(size_t)(nBase + ldRow + 32 * p) * DIMC + ldCol];
    }

    for (int k0 = 0; k0 < DIMC; k0 += 32) {
        __syncthreads();
#pragma unroll
        for (int p = 0; p < 4; p++) {
            float4 ta;
            ta.x = to_tf32(ra[p].x); ta.y = to_tf32(ra[p].y);
            ta.z = to_tf32(ra[p].z); ta.w = to_tf32(ra[p].w);
            *(float4*)&As[ldRow + 32 * p][ldCol] = ta;
            float4 tb;
            tb.x = to_tf32(rb[p].x); tb.y = to_tf32(rb[p].y);
            tb.z = to_tf32(rb[p].z); tb.w = to_tf32(rb[p].w);
            *(float4*)&Bs[ldRow + 32 * p][ldCol] = tb;
        }
        __syncthreads();

        if (k0 + 32 < DIMC) {
            const int kn = k0 + 32;
#pragma unroll
            for (int p = 0; p < 4; p++) {
                ra[p] = *(const float4*)&A[(size_t)(mBase + ldRow + 32 * p) * DIMC + kn + ldCol];
                rb[p] = *(const float4*)&W[(size_t)(nBase + ldRow + 32 * p) * DIMC + kn + ldCol];
            }
        }

#pragma unroll
        for (int kk = 0; kk < 32; kk += 8) {
            uint32_t a[4][4];
#pragma unroll
            for (int mi = 0; mi < 4; mi++) {
                const int r = wm * 64 + mi * 16 + (lane >> 2);
                const int col = kk + (lane & 3);
                a[mi][0] = fbits(As[r][col]);
                a[mi][1] = fbits(As[r + 8][col]);
                a[mi][2] = fbits(As[r][col + 4]);
                a[mi][3] = fbits(As[r + 8][col + 4]);
            }
#pragma unroll
            for (int nf = 0; nf < 4; nf++) {
                const int n = wn * 32 + nf * 8 + (lane >> 2);
                const int col = kk + (lane & 3);
                const uint32_t b0 = fbits(Bs[n][col]);
                const uint32_t b1 = fbits(Bs[n][col + 4]);
#pragma unroll
                for (int mi = 0; mi < 4; mi++) mma_tf32(c[mi][nf], a[mi], b0, b1);
            }
        }
    }

#pragma unroll
    for (int mi = 0; mi < 4; mi++) {
        const int gm = mBase + wm * 64 + mi * 16 + (lane >> 2);
        const int b = gm >> 11;
        const int n = gm & 2047;
#pragma unroll
        for (int nf = 0; nf < 4; nf++) {
            const int gn = nBase + wn * 32 + nf * 8 + ((lane & 3) << 1);
            const int h = gn >> 6;
            const int j = gn & 63;
            const size_t base = (((size_t)(b * 16 + h) * SEQ) + n) * 64 + j;
            *(float2*)&Out[base] =
                make_float2(to_tf32(c[mi][nf][0] * scale), to_tf32(c[mi][nf][1] * scale));
            *(float2*)&Out[base + 8 * 64] =
                make_float2(to_tf32(c[mi][nf][2] * scale), to_tf32(c[mi][nf][3] * scale));
        }
    }
}

// Fused K+V projection (R10 256-thread version — banked best): one pass over
// the shared A (kv activations) tile, two B tiles (Wk, Wv), two accumulator
// sets. Each A-fragment LDS feeds 8 MMAs.
__global__ void __launch_bounds__(256, 1) proj_kv(const float* __restrict__ A,
                                                  const float* __restrict__ Wk,
                                                  const float* __restrict__ Wv,
                                                  float* __restrict__ OutK,
                                                  float* __restrict__ OutV) {
    // dynamic smem: As[128][36] @0, Bk[128][36] @4608, Bv[128][36] @9216 (floats)
    extern __shared__ float psm[];
    float (*As)[36] = (float (*)[36])psm;
    float (*Bk)[36] = (float (*)[36])(psm + 4608);
    float (*Bv)[36] = (float (*)[36])(psm + 9216);

    const int tid = threadIdx.x;
    const int lane = tid & 31;
    const int warp = tid >> 5;
    const int wm = warp & 1;
    const int wn = warp >> 1;
    const int mBase = blockIdx.y * 128;
    const int nBase = blockIdx.x * 128;

    float c[2][4][4][4];
#pragma unroll
    for (int kv = 0; kv < 2; kv++)
#pragma unroll
        for (int i = 0; i < 4; i++)
#pragma unroll
            for (int j = 0; j < 4; j++)
#pragma unroll
                for (int k = 0; k < 4; k++) c[kv][i][j][k] = 0.f;

    const int ldRow = tid >> 3;
    const int ldCol = (tid & 7) << 2;

    float4 ra[4], rbk[4], rbv[4];
#pragma unroll
    for (int p = 0; p < 4; p++) {
        const size_t rowA = (size_t)(mBase + ldRow + 32 * p) * DIMC + ldCol;
        const size_t rowB = (size_t)(nBase + ldRow + 32 * p) * DIMC + ldCol;
        ra[p]  = *(const float4*)&A[rowA];
        rbk[p] = *(const float4*)&Wk[rowB];
        rbv[p] = *(const float4*)&Wv[rowB];
    }

    for (int k0 = 0; k0 < DIMC; k0 += 32) {
        __syncthreads();
#pragma unroll
        for (int p = 0; p < 4; p++) {
            float4 t;
            t.x = to_tf32(ra[p].x); t.y = to_tf32(ra[p].y);
            t.z = to_tf32(ra[p].z); t.w = to_tf32(ra[p].w);
            *(float4*)&As[ldRow + 32 * p][ldCol] = t;
            t.x = to_tf32(rbk[p].x); t.y = to_tf32(rbk[p].y);
            t.z = to_tf32(rbk[p].z); t.w = to_tf32(rbk[p].w);
            *(float4*)&Bk[ldRow + 32 * p][ldCol] = t;
            t.x = to_tf32(rbv[p].x); t.y = to_tf32(rbv[p].y);
            t.z = to_tf32(rbv[p].z); t.w = to_tf32(rbv[p].w);
            *(float4*)&Bv[ldRow + 32 * p][ldCol] = t;
        }
        __syncthreads();

        if (k0 + 32 < DIMC) {
            const int kn = k0 + 32;
#pragma unroll
            for (int p = 0; p < 4; p++) {
                const size_t rowA = (size_t)(mBase + ldRow + 32 * p) * DIMC + kn + ldCol;
                const size_t rowB = (size_t)(nBase + ldRow + 32 * p) * DIMC + kn + ldCol;
                ra[p]  = *(const float4*)&A[rowA];
                rbk[p] = *(const float4*)&Wk[rowB];
                rbv[p] = *(const float4*)&Wv[rowB];
            }
        }

#pragma unroll
        for (int kk = 0; kk < 32; kk += 8) {
            uint32_t a[4][4];
#pragma unroll
            for (int mi = 0; mi < 4; mi++) {
                const int r = wm * 64 + mi * 16 + (lane >> 2);
                const int col = kk + (lane & 3);
                a[mi][0] = fbits(As[r][col]);
                a[mi][1] = fbits(As[r + 8][col]);
                a[mi][2] = fbits(As[r][col + 4]);
                a[mi][3] = fbits(As[r + 8][col + 4]);
            }
#pragma unroll
            for (int nf = 0; nf < 4; nf++) {
                const int n = wn * 32 + nf * 8 + (lane >> 2);
                const int col = kk + (lane & 3);
                const uint32_t bk0 = fbits(Bk[n][col]);
                const uint32_t bk1 = fbits(Bk[n][col + 4]);
                const uint32_t bv0 = fbits(Bv[n][col]);
                const uint32_t bv1 = fbits(Bv[n][col + 4]);
#pragma unroll
                for (int mi = 0; mi < 4; mi++) {
                    mma_tf32(c[0][mi][nf], a[mi], bk0, bk1);
                    mma_tf32(c[1][mi][nf], a[mi], bv0, bv1);
                }
            }
        }
    }

#pragma unroll
    for (int mi = 0; mi < 4; mi++) {
        const int gm = mBase + wm * 64 + mi * 16 + (lane >> 2);
        const int b = gm >> 11;
        const int n = gm & 2047;
#pragma unroll
        for (int nf = 0; nf < 4; nf++) {
            const int gn = nBase + wn * 32 + nf * 8 + ((lane & 3) << 1);
            const int h = gn >> 6;
            const int j = gn & 63;
            const size_t base = (((size_t)(b * 16 + h) * SEQ) + n) * 64 + j;
            *(float2*)&OutK[base] =
                make_float2(to_tf32(c[0][mi][nf][0]), to_tf32(c[0][mi][nf][1]));
            *(float2*)&OutK[base + 8 * 64] =
                make_float2(to_tf32(c[0][mi][nf][2]), to_tf32(c[0][mi][nf][3]));
            *(float2*)&OutV[base] =
                make_float2(to_tf32(c[1][mi][nf][0]), to_tf32(c[1][mi][nf][1]));
            *(float2*)&OutV[base + 8 * 64] =
                make_float2(to_tf32(c[1][mi][nf][2]), to_tf32(c[1][mi][nf][3]));
        }
    }
}

// Flash attention, single-pass streaming softmax. Q lives in PERSISTENT smem
// so registers fit 3 CTAs/SM (12 warps). Q prologue is now cp.async (own
// commit group, FIFO-ordered before tile 0 so the existing wait covers it).
// K/V double-buffered cp.async; V rows permuted even-first so the S C-frag
// feeds PV as an A-fragment with no shuffles; row-sum l computed by the PV MMA
// via a ones-column in the V tile padding; P fed as raw fp32 (HW tf32
// truncation, bias cancels in O/l).
// Smem floats: Qs[128][68] @0 (8704), K 2x[32][68] @8704, V 2x[32][72] @13056.
static constexpr int ATTN_SMEM_FLOATS = 128 * 68 + 2 * 32 * 68 + 2 * 32 * 72;  // 17664
__global__ void __launch_bounds__(128, 3) attn(const float* __restrict__ Q,
                                               const float* __restrict__ K,
                                               const float* __restrict__ V,
                                               float* __restrict__ Out) {
    extern __shared__ float sm[];
    float (*Qs)[68] = (float (*)[68])sm;

    const int tid = threadIdx.x;
    const int lane = tid & 31;
    const int warp = tid >> 5;
    const int bh = blockIdx.y;
    const int qBase = blockIdx.x * 128;
    const float* Qg = Q + (size_t)bh * SEQ * 64;
    const float* Kg = K + (size_t)bh * SEQ * 64;
    const float* Vg = V + (size_t)bh * SEQ * 64;

    const int chRow = tid >> 4;            // rows 0..7 (+8 per i)
    const int chCol = (tid & 15) << 2;     // float col 0..60
    const int vRow = (chRow >> 1) + ((chRow & 1) << 2);  // even-first permutation
    const uint32_t qDst0 = smem_u32(&sm[0]) + (uint32_t)(chRow * 68 + chCol) * 4u;
    const uint32_t kDst0 = smem_u32(&sm[8704]) + (uint32_t)(chRow * 68 + chCol) * 4u;
    const uint32_t vDst0 = smem_u32(&sm[13056]) + (uint32_t)(vRow * 72 + chCol) * 4u;

    // --- Prologue: Q tile (128 rows) via cp.async, own commit group ---
#pragma unroll
    for (int i = 0; i < 16; i++) {
        const int row = chRow + 8 * i;
        cp16(qDst0 + i * (8 * 68 * 4), &Qg[(size_t)(qBase + row) * 64 + chCol]);
    }
    cp_commit();

    // Ones-column init: V tile cols 64..71 (never touched by cp.async).
    // col 64 = 1.0 (l accumulator column), 65..71 = 0. Both buffers.
    if (tid < 64) {
        const int buf = tid >> 5;
        const int row = tid & 31;
        float* p = &sm[13056 + buf * 2304 + row * 72 + 64];
        *(float4*)&p[0] = make_float4(1.f, 0.f, 0.f, 0.f);
        *(float4*)&p[4] = make_float4(0.f, 0.f, 0.f, 0.f);
    }

    auto issue_tile = [&](int t) {
        const int buf = t & 1;
        const int kvBase = t * 32;
        const uint32_t kD = kDst0 + buf * (2176 * 4);
        const uint32_t vD = vDst0 + buf * (2304 * 4);
#pragma unroll
        for (int i = 0; i < 4; i++) {
            const int row = chRow + 8 * i;
            cp16(kD + i * (8 * 68 * 4), &Kg[(size_t)(kvBase + row) * 64 + chCol]);
            cp16(vD + i * (8 * 72 * 4), &Vg[(size_t)(kvBase + row) * 64 + chCol]);
        }
        cp_commit();
    };

    constexpr int T = SEQ / 32;
    issue_tile(0);
    issue_tile(1);

    // Accumulators: nf 0..7 = O columns, nf 8 = {l, garbage} columns 64..71.
    float o[2][9][4];
#pragma unroll
    for (int mi = 0; mi < 2; mi++)
#pragma unroll
        for (int nf = 0; nf < 9; nf++)
#pragma unroll
            for (int k = 0; k < 4; k++) o[mi][nf][k] = 0.f;

    const int rq = warp * 32 + (lane >> 2);

    for (int t = 0; t < T; t++) {
        // Pending groups at t=0: {Q, t0, t1} — wait<1> drains Q and t0 (FIFO).
        if (t < T - 1) cp_wait<1>(); else cp_wait<0>();
        __syncthreads();

        const int buf = t & 1;
        const float(*Ks)[68] = (const float(*)[68])&sm[8704 + buf * 2176];
        const float(*Vs)[72] = (const float(*)[72])&sm[13056 + buf * 2304];

        // S = Q K^T (log2-domain: Q pre-scaled by log2e/8).
        // Q fragments re-read from smem each kk; each K B-frag feeds 2 MMAs.
        float s[2][4][4];
#pragma unroll
        for (int mi = 0; mi < 2; mi++)
#pragma unroll
            for (int nf = 0; nf < 4; nf++)
#pragma unroll
                for (int k = 0; k < 4; k++) s[mi][nf][k] = 0.f;

#pragma unroll
        for (int kk = 0; kk < 8; kk++) {
            const int col = kk * 8 + (lane & 3);
            uint32_t a0[4], a1[4];
            a0[0] = fbits(Qs[rq][col]);
            a0[1] = fbits(Qs[rq + 8][col]);
            a0[2] = fbits(Qs[rq][col + 4]);
            a0[3] = fbits(Qs[rq + 8][col + 4]);
            a1[0] = fbits(Qs[rq + 16][col]);
            a1[1] = fbits(Qs[rq + 24][col]);
            a1[2] = fbits(Qs[rq + 16][col + 4]);
            a1[3] = fbits(Qs[rq + 24][col + 4]);
#pragma unroll
            for (int nf = 0; nf < 4; nf++) {
                const int n = nf * 8 + (lane >> 2);
                const uint32_t b0 = fbits(Ks[n][col]);
                const uint32_t b1 = fbits(Ks[n][col + 4]);
                mma_tf32(s[0][nf], a0, b0, b1);
                mma_tf32(s[1][nf], a1, b0, b1);
            }
        }

        // p = exp2(s); no scalar l accumulation (handled by the ones-column MMA)
#pragma unroll
        for (int mi = 0; mi < 2; mi++)
#pragma unroll
            for (int nf = 0; nf < 4; nf++) {
                s[mi][nf][0] = exp2f(s[mi][nf][0]);
                s[mi][nf][1] = exp2f(s[mi][nf][1]);
                s[mi][nf][2] = exp2f(s[mi][nf][2]);
                s[mi][nf][3] = exp2f(s[mi][nf][3]);
            }

        // O += P V (and l += P·1 via nf=8), shuffle-free via the even-first V
        // row permutation; P fed as raw fp32 (HW tf32 truncation).
#pragma unroll
        for (int kt = 0; kt < 4; kt++) {
            uint32_t a0[4], a1[4];
            a0[0] = fbits(s[0][kt][0]);
            a0[1] = fbits(s[0][kt][2]);
            a0[2] = fbits(s[0][kt][1]);
            a0[3] = fbits(s[0][kt][3]);
            a1[0] = fbits(s[1][kt][0]);
            a1[1] = fbits(s[1][kt][2]);
            a1[2] = fbits(s[1][kt][1]);
            a1[3] = fbits(s[1][kt][3]);
#pragma unroll
            for (int nf = 0; nf < 9; nf++) {
                const int n = nf * 8 + (lane >> 2);
                const uint32_t b0 = fbits(Vs[kt * 8 + (lane & 3)][n]);
                const uint32_t b1 = fbits(Vs[kt * 8 + (lane & 3) + 4][n]);
                mma_tf32(o[0][nf], a0, b0, b1);
                mma_tf32(o[1][nf], a1, b0, b1);
            }
        }

        __syncthreads();   // all warps done with buf before it is refilled
        if (t + 2 < T) issue_tile(t + 2);
    }

    // l lives in column 64 = C-frag regs {0,2} of lanes with (lane&3)==0.
    // Broadcast from the quad leader to all 4 lanes.
    const int qlead = lane & ~3;
    float ls[2][2];
#pragma unroll
    for (int mi = 0; mi < 2; mi++) {
        ls[mi][0] = __shfl_sync(FULL_MASK, o[mi][8][0], qlead);
        ls[mi][1] = __shfl_sync(FULL_MASK, o[mi][8][2], qlead);
    }

    // epilogue: Out[b, q, h*64 + j] = O / l
    const int b = bh >> 4;
    const int h = bh & 15;
#pragma unroll
    for (int mi = 0; mi < 2; mi++) {
        const float inv0 = 1.f / ls[mi][0];
        const float inv1 = 1.f / ls[mi][1];
        const int r0 = qBase + warp * 32 + mi * 16 + (lane >> 2);
#pragma unroll
        for (int nf = 0; nf < 8; nf++) {
            const int col = h * 64 + nf * 8 + ((lane & 3) << 1);
            const size_t i0 = ((size_t)b * SEQ + r0) * DIMC + col;
            *(float2*)&Out[i0] =
                make_float2(o[mi][nf][0] * inv0, o[mi][nf][1] * inv0);
            *(float2*)&Out[i0 + (size_t)8 * DIMC] =
                make_float2(o[mi][nf][2] * inv1, o[mi][nf][3] * inv1);
        }
    }
}

extern "C" void kernel_launch(void* const* d_in, const int* in_sizes, int n_in,
                              void* d_out, int out_size) {
    const float* x  = (const float*)d_in[0];
    const float* kv = (const float*)d_in[1];
    const float* Wq = (const float*)d_in[2];
    const float* Wk = (const float*)d_in[3];
    const float* Wv = (const float*)d_in[4];
    float* out = (float*)d_out;

    float *Qg, *Kg, *Vg;
    cudaGetSymbolAddress((void**)&Qg, g_Q);
    cudaGetSymbolAddress((void**)&Kg, g_K);
    cudaGetSymbolAddress((void**)&Vg, g_V);

    // One-time host-object setup (no device memory: streams/events/attrs only).
    static cudaStream_t s2 = nullptr;
    static cudaEvent_t eFork = nullptr, eJoin = nullptr;
    if (s2 == nullptr) {
        cudaStreamCreateWithFlags(&s2, cudaStreamNonBlocking);
        cudaEventCreateWithFlags(&eFork, cudaEventDisableTiming);
        cudaEventCreateWithFlags(&eJoin, cudaEventDisableTiming);
        cudaFuncSetAttribute(proj_kv, cudaFuncAttributeMaxDynamicSharedMemorySize,
                             3 * 128 * 36 * 4);   // 55296 bytes
        cudaFuncSetAttribute(attn, cudaFuncAttributeMaxDynamicSharedMemorySize,
                             ATTN_SMEM_FLOATS * 4);   // 70656 bytes
    }

    // Fold (1/sqrt(64)) * log2(e) into the Q projection so the attention
    // softmax uses bare exp2.
    const float qscale = 0.125f * 1.44269504088896f;

    dim3 gg(DIMC / 128, (4 * SEQ) / 128);   // (8, 64)

    // Fork: Q projection on s2 concurrently with the fused K/V projection on
    // the main (captured) stream; join before attn.
    cudaEventRecord(eFork, 0);
    cudaStreamWaitEvent(s2, eFork, 0);
    proj_gemm<<<gg, 256, 0, s2>>>(x, Wq, Qg, qscale);
    proj_kv<<<gg, 256, 3 * 128 * 36 * 4>>>(kv, Wk, Wv, Kg, Vg);
    cudaEventRecord(eJoin, s2);
    cudaStreamWaitEvent(0, eJoin, 0);

    attn<<<dim3(SEQ / 128, 64), 128, ATTN_SMEM_FLOATS * 4>>>(Qg, Kg, Vg, out);
}